// round 2
// baseline (speedup 1.0000x reference)
#include <cuda_runtime.h>

// Problem constants
#define B_    32
#define TH    256
#define TQ    64
#define DIN   256
#define DD    256   // internal dim
#define KD    256   // reduction dim of projections

// Scratch for projections (allocation-free rule: __device__ globals)
__device__ float g_kp[B_ * TH * DD];   // 8 MB
__device__ float g_qp[B_ * TQ * DD];   // 2 MB

__device__ __forceinline__ float tanh_fast(float x) {
    float y;
    asm("tanh.approx.f32 %0, %1;" : "=f"(y) : "f"(x));
    return y;
}

// ---------------------------------------------------------------------------
// Kernel 1: combined projection GEMM.
//   g_kp[(b*TH+t), d] = sum_k inputs[(b*TH+t), k] * w1[d, k]   (M = 8192)
//   g_qp[(b*TQ+q), d] = sum_k state [(b*TQ+q), k] * w2[d, k]   (M = 2048)
// Tiles: BM=BN=64, BK=16, 256 threads, 4x4 micro-tile, float4 SMEM reads.
// grid = (128 + 32 M-tiles, 4 N-tiles). All dims divide evenly -> no guards.
// ---------------------------------------------------------------------------
__global__ __launch_bounds__(256) void proj_gemm(
    const float* __restrict__ inputs, const float* __restrict__ state,
    const float* __restrict__ w1, const float* __restrict__ w2)
{
    const int PAD = 68;   // 68*4B = 272B = 17*16B -> float4 aligned rows
    __shared__ __align__(16) float As[16 * PAD];
    __shared__ __align__(16) float Bs[16 * PAD];

    const float* A;
    const float* W;
    float* C;
    int m0;
    if (blockIdx.x < 128) {           // kp tiles (8192 rows / 64)
        A = inputs; W = w1; C = g_kp; m0 = blockIdx.x * 64;
    } else {                          // qp tiles (2048 rows / 64)
        A = state;  W = w2; C = g_qp; m0 = (blockIdx.x - 128) * 64;
    }
    const int n0  = blockIdx.y * 64;
    const int tid = threadIdx.x;
    const int tx  = tid & 15;         // n-direction micro group
    const int ty  = tid >> 4;         // m-direction micro group
    const int lrow = tid >> 2;        // 0..63 (row loaded by this thread)
    const int lk4  = (tid & 3) << 2;  // 0,4,8,12 (k offset of the float4)

    float acc[4][4];
#pragma unroll
    for (int i = 0; i < 4; i++)
#pragma unroll
        for (int j = 0; j < 4; j++) acc[i][j] = 0.f;

    for (int kt = 0; kt < KD; kt += 16) {
        float4 av = *(const float4*)&A[(size_t)(m0 + lrow) * KD + kt + lk4];
        float4 wv = *(const float4*)&W[(size_t)(n0 + lrow) * KD + kt + lk4];
        __syncthreads();   // previous compute done before overwriting smem
        As[(lk4 + 0) * PAD + lrow] = av.x;
        As[(lk4 + 1) * PAD + lrow] = av.y;
        As[(lk4 + 2) * PAD + lrow] = av.z;
        As[(lk4 + 3) * PAD + lrow] = av.w;
        Bs[(lk4 + 0) * PAD + lrow] = wv.x;
        Bs[(lk4 + 1) * PAD + lrow] = wv.y;
        Bs[(lk4 + 2) * PAD + lrow] = wv.z;
        Bs[(lk4 + 3) * PAD + lrow] = wv.w;
        __syncthreads();
#pragma unroll
        for (int kk = 0; kk < 16; kk++) {
            float4 aa = *(const float4*)&As[kk * PAD + ty * 4];
            float4 bb = *(const float4*)&Bs[kk * PAD + tx * 4];
            float ar[4] = {aa.x, aa.y, aa.z, aa.w};
            float br[4] = {bb.x, bb.y, bb.z, bb.w};
#pragma unroll
            for (int i = 0; i < 4; i++)
#pragma unroll
                for (int j = 0; j < 4; j++)
                    acc[i][j] = fmaf(ar[i], br[j], acc[i][j]);
        }
    }

#pragma unroll
    for (int i = 0; i < 4; i++) {
        float4 o = make_float4(acc[i][0], acc[i][1], acc[i][2], acc[i][3]);
        *(float4*)&C[(size_t)(m0 + ty * 4 + i) * DD + n0 + tx * 4] = o;
    }
}

// ---------------------------------------------------------------------------
// Kernel 2: scores + softmax + context, fused.
// grid = (TQ/8, B). Block = 256 threads = 8 warps; warp w handles query
// q = blockIdx.x*8 + w. kp / keys rows staged 16 at a time in SMEM.
// Lane d-ownership: d = j*32 + lane (j = 0..7) -> conflict-free LDS.
// ---------------------------------------------------------------------------
__global__ __launch_bounds__(256) void attn_kernel(
    const float* __restrict__ keys, const float* __restrict__ v,
    float* __restrict__ out)
{
    __shared__ __align__(16) float stage[16][256];  // 16 KB staging
    __shared__ float sc[8][256];                    // per-warp scores/alpha

    const int b    = blockIdx.y;
    const int warp = threadIdx.x >> 5;
    const int lane = threadIdx.x & 31;
    const int q    = blockIdx.x * 8 + warp;

    const float* kp = g_kp + (size_t)b * TH * DD;
    const float* qp = g_qp + (size_t)(b * TQ + q) * DD;

    float vv[8], qv[8];
#pragma unroll
    for (int j = 0; j < 8; j++) {
        int d = j * 32 + lane;
        vv[j] = v[d];
        qv[j] = qp[d];
    }

    // ---- scores[t] = sum_d v[d] * tanh(qp[d] + kp[t,d]) ----
    for (int t0 = 0; t0 < TH; t0 += 16) {
        __syncthreads();
#pragma unroll
        for (int s = 0; s < 4; s++) {
            int i = threadIdx.x + s * 256;   // float4 index 0..1023
            int r = i >> 6;                  // row within chunk (64 f4/row)
            int c = (i & 63) << 2;
            *(float4*)&stage[r][c] = *(const float4*)&kp[(size_t)(t0 + r) * DD + c];
        }
        __syncthreads();
        for (int tt = 0; tt < 16; tt++) {
            float s = 0.f;
#pragma unroll
            for (int j = 0; j < 8; j++) {
                float x = qv[j] + stage[tt][j * 32 + lane];
                s = fmaf(vv[j], tanh_fast(x), s);
            }
#pragma unroll
            for (int o = 16; o; o >>= 1) s += __shfl_xor_sync(0xffffffffu, s, o);
            if (lane == 0) sc[warp][t0 + tt] = s;
        }
    }
    __syncwarp();

    // ---- softmax over t (warp-private row of sc) ----
    float ls[8];
    float mval = -1e30f;
#pragma unroll
    for (int j = 0; j < 8; j++) {
        ls[j] = sc[warp][j * 32 + lane];
        mval = fmaxf(mval, ls[j]);
    }
#pragma unroll
    for (int o = 16; o; o >>= 1) mval = fmaxf(mval, __shfl_xor_sync(0xffffffffu, mval, o));
    float ssum = 0.f;
#pragma unroll
    for (int j = 0; j < 8; j++) {
        ls[j] = __expf(ls[j] - mval);
        ssum += ls[j];
    }
#pragma unroll
    for (int o = 16; o; o >>= 1) ssum += __shfl_xor_sync(0xffffffffu, ssum, o);
    const float inv = 1.f / ssum;
#pragma unroll
    for (int j = 0; j < 8; j++) sc[warp][j * 32 + lane] = ls[j] * inv;
    __syncwarp();

    // ---- context[i] = sum_t alpha[t] * keys[b,t,i] ----
    float ctx[8];
#pragma unroll
    for (int j = 0; j < 8; j++) ctx[j] = 0.f;
    const float* kb = keys + (size_t)b * TH * DIN;

    for (int t0 = 0; t0 < TH; t0 += 16) {
        __syncthreads();
#pragma unroll
        for (int s = 0; s < 4; s++) {
            int i = threadIdx.x + s * 256;
            int r = i >> 6;
            int c = (i & 63) << 2;
            *(float4*)&stage[r][c] = *(const float4*)&kb[(size_t)(t0 + r) * DIN + c];
        }
        __syncthreads();
        for (int tt = 0; tt < 16; tt++) {
            float a = sc[warp][t0 + tt];   // broadcast LDS
#pragma unroll
            for (int j = 0; j < 8; j++)
                ctx[j] = fmaf(a, stage[tt][j * 32 + lane], ctx[j]);
        }
    }

    float* o = out + (size_t)(b * TQ + q) * DIN;
#pragma unroll
    for (int j = 0; j < 8; j++) o[j * 32 + lane] = ctx[j];
}

// ---------------------------------------------------------------------------
// Launch. Inputs (metadata order): inputs, state, w1, w2, v, batch_size.
// Output: (B*TQ, DIN) float32.
// ---------------------------------------------------------------------------
extern "C" void kernel_launch(void* const* d_in, const int* in_sizes, int n_in,
                              void* d_out, int out_size)
{
    const float* inputs = (const float*)d_in[0];
    const float* state  = (const float*)d_in[1];
    const float* w1     = (const float*)d_in[2];
    const float* w2     = (const float*)d_in[3];
    const float* v      = (const float*)d_in[4];
    float* out = (float*)d_out;
    (void)in_sizes; (void)n_in; (void)out_size;

    dim3 g1(128 + 32, 4);      // 160 M-tiles x 4 N-tiles, 256 threads
    proj_gemm<<<g1, 256>>>(inputs, state, w1, w2);

    dim3 g2(TQ / 8, B_);       // (8, 32) blocks, 8 warps = 8 queries each
    attn_kernel<<<g2, 256>>>(inputs, v, out);
}

// round 3
// speedup vs baseline: 1.2866x; 1.2866x over previous
#include <cuda_runtime.h>

// Problem constants
#define B_    32
#define TH    256
#define TQ    64
#define DIN   256
#define DD    256   // internal dim
#define KD    256   // reduction dim of projections

// Scratch (allocation-free rule: __device__ globals)
__device__ float g_kpT[B_ * DD * TH];  // 8 MB, TRANSPOSED: [b][d][t]
__device__ float g_qp [B_ * TQ * DD];  // 2 MB, [b*TQ+q][d]

__device__ __forceinline__ float tanh_fast(float x) {
    float y;
    asm("tanh.approx.f32 %0, %1;" : "=f"(y) : "f"(x));
    return y;
}

// ---------------------------------------------------------------------------
// Kernel 1: combined projection GEMM.
//   g_kpT[b][d][t] = sum_k inputs[(b*TH+t), k] * w1[d, k]   (transposed store)
//   g_qp[(b*TQ+q), d] = sum_k state[(b*TQ+q), k] * w2[d, k]
// Tiles: BM=BN=64, BK=16, 256 threads, 4x4 micro-tile.
// Micro-tile mapping: ty = tid&15 (m, fast) so the transposed kp store
// (float4 along t) is coalesced across lanes.
// ---------------------------------------------------------------------------
__global__ __launch_bounds__(256) void proj_gemm(
    const float* __restrict__ inputs, const float* __restrict__ state,
    const float* __restrict__ w1, const float* __restrict__ w2)
{
    const int PAD = 68;   // 68*4B = 272B -> float4-aligned k-rows
    __shared__ __align__(16) float As[16 * PAD];
    __shared__ __align__(16) float Bs[16 * PAD];

    const bool is_kp = (blockIdx.x < 128);
    const float* A;
    const float* W;
    int m0;
    if (is_kp) { A = inputs; W = w1; m0 = blockIdx.x * 64; }
    else       { A = state;  W = w2; m0 = (blockIdx.x - 128) * 64; }

    const int n0  = blockIdx.y * 64;
    const int tid = threadIdx.x;
    const int ty  = tid & 15;         // m-direction micro group (fast)
    const int tx  = tid >> 4;         // n-direction micro group (slow)
    const int lrow = tid >> 2;        // 0..63
    const int lk4  = (tid & 3) << 2;  // 0,4,8,12

    float acc[4][4];
#pragma unroll
    for (int i = 0; i < 4; i++)
#pragma unroll
        for (int j = 0; j < 4; j++) acc[i][j] = 0.f;

    for (int kt = 0; kt < KD; kt += 16) {
        float4 av = *(const float4*)&A[(size_t)(m0 + lrow) * KD + kt + lk4];
        float4 wv = *(const float4*)&W[(size_t)(n0 + lrow) * KD + kt + lk4];
        __syncthreads();
        As[(lk4 + 0) * PAD + lrow] = av.x;
        As[(lk4 + 1) * PAD + lrow] = av.y;
        As[(lk4 + 2) * PAD + lrow] = av.z;
        As[(lk4 + 3) * PAD + lrow] = av.w;
        Bs[(lk4 + 0) * PAD + lrow] = wv.x;
        Bs[(lk4 + 1) * PAD + lrow] = wv.y;
        Bs[(lk4 + 2) * PAD + lrow] = wv.z;
        Bs[(lk4 + 3) * PAD + lrow] = wv.w;
        __syncthreads();
#pragma unroll
        for (int kk = 0; kk < 16; kk++) {
            float4 aa = *(const float4*)&As[kk * PAD + ty * 4];
            float4 bb = *(const float4*)&Bs[kk * PAD + tx * 4];
            float ar[4] = {aa.x, aa.y, aa.z, aa.w};
            float br[4] = {bb.x, bb.y, bb.z, bb.w};
#pragma unroll
            for (int i = 0; i < 4; i++)
#pragma unroll
                for (int j = 0; j < 4; j++)
                    acc[i][j] = fmaf(ar[i], br[j], acc[i][j]);
        }
    }

    if (is_kp) {
        // transposed store: float4 along t (coalesced: ty is the fast index)
        const int b  = m0 >> 8;
        const int t0 = m0 & 255;
#pragma unroll
        for (int j = 0; j < 4; j++) {
            float4 o = make_float4(acc[0][j], acc[1][j], acc[2][j], acc[3][j]);
            *(float4*)&g_kpT[(size_t)(b * DD + n0 + tx * 4 + j) * TH + t0 + ty * 4] = o;
        }
    } else {
        // normal store [q][d] (scattered across lanes; qp is only 2 MB)
#pragma unroll
        for (int i = 0; i < 4; i++) {
            float4 o = make_float4(acc[i][0], acc[i][1], acc[i][2], acc[i][3]);
            *(float4*)&g_qp[(size_t)(m0 + ty * 4 + i) * DD + n0 + tx * 4] = o;
        }
    }
}

// ---------------------------------------------------------------------------
// Kernel 2: scores + softmax + context, fused. grid = (TQ/8, B), 256 thr.
// Score phase: lanes own t (no per-t reductions!). Warp w: t-half = w>>2,
// query pair = w&3 (2 queries per warp -> kp LDS amortized 2x).
// Context phase: warp w owns i-slice [w*32, w*32+32), alphas via float4
// broadcast LDS, keys staged 16 t-rows at a time.
// ---------------------------------------------------------------------------
__global__ __launch_bounds__(256) void attn_kernel(
    const float* __restrict__ keys, const float* __restrict__ v,
    float* __restrict__ out)
{
    __shared__ __align__(16) float stage[16][260];  // staging (PAD 260: f4-aligned rows)
    __shared__ __align__(16) float sc[8][256];      // scores -> alpha
    __shared__ __align__(16) float sqp[8][256];     // q projections for this block
    __shared__ float sv[256];                       // v vector

    const int b    = blockIdx.y;
    const int q0   = blockIdx.x * 8;
    const int tid  = threadIdx.x;
    const int warp = tid >> 5;
    const int lane = tid & 31;
    const int half  = warp >> 2;       // t-half (0 or 1)
    const int pair  = warp & 3;        // query pair within block
    const int tbase = half * 128;

    // preload sqp, sv
    sv[tid] = v[tid];
#pragma unroll
    for (int s = 0; s < 8; s++) {
        int idx = tid + s * 256;
        int q = idx >> 8, d = idx & 255;
        sqp[q][d] = g_qp[(size_t)(b * TQ + q0 + q) * DD + d];
    }

    // ---- scores: s[q][t] = sum_d v[d] * tanh(qp[q][d] + kp[d][t]) ----
    float s0[4] = {0.f, 0.f, 0.f, 0.f};
    float s1[4] = {0.f, 0.f, 0.f, 0.f};
    const float* kpT = g_kpT + (size_t)b * DD * TH;

    for (int c = 0; c < 16; c++) {
        const int d0 = c * 16;
        __syncthreads();
#pragma unroll
        for (int s = 0; s < 4; s++) {
            int idx = tid + s * 256;
            int r  = idx >> 6;           // d-row 0..15
            int c4 = (idx & 63) << 2;    // t column (step 4)
            *(float4*)&stage[r][c4] = *(const float4*)&kpT[(size_t)(d0 + r) * TH + c4];
        }
        __syncthreads();
#pragma unroll
        for (int dd = 0; dd < 16; dd++) {
            float vd = sv[d0 + dd];
            float qa = sqp[2 * pair + 0][d0 + dd];
            float qb = sqp[2 * pair + 1][d0 + dd];
#pragma unroll
            for (int j = 0; j < 4; j++) {
                float x = stage[dd][tbase + j * 32 + lane];
                s0[j] = fmaf(vd, tanh_fast(qa + x), s0[j]);
                s1[j] = fmaf(vd, tanh_fast(qb + x), s1[j]);
            }
        }
    }
#pragma unroll
    for (int j = 0; j < 4; j++) {
        sc[2 * pair + 0][tbase + j * 32 + lane] = s0[j];
        sc[2 * pair + 1][tbase + j * 32 + lane] = s1[j];
    }
    __syncthreads();

    // ---- softmax over t: warps 0-3 handle 2 queries each ----
    if (warp < 4) {
#pragma unroll
        for (int qq = 0; qq < 2; qq++) {
            int q = 2 * warp + qq;
            float ls[8];
            float m = -1e30f;
#pragma unroll
            for (int j = 0; j < 8; j++) {
                ls[j] = sc[q][j * 32 + lane];
                m = fmaxf(m, ls[j]);
            }
#pragma unroll
            for (int o = 16; o; o >>= 1) m = fmaxf(m, __shfl_xor_sync(0xffffffffu, m, o));
            float ssum = 0.f;
#pragma unroll
            for (int j = 0; j < 8; j++) {
                ls[j] = __expf(ls[j] - m);
                ssum += ls[j];
            }
#pragma unroll
            for (int o = 16; o; o >>= 1) ssum += __shfl_xor_sync(0xffffffffu, ssum, o);
            float inv = 1.f / ssum;
#pragma unroll
            for (int j = 0; j < 8; j++) sc[q][j * 32 + lane] = ls[j] * inv;
        }
    }

    // ---- context[i] = sum_t alpha[t] * keys[b][t][i]; warp owns 32 i ----
    float ctx[8];
#pragma unroll
    for (int q = 0; q < 8; q++) ctx[q] = 0.f;
    const float* kb = keys + (size_t)b * TH * DIN;
    const int ilane = warp * 32 + lane;

    for (int c = 0; c < 16; c++) {
        const int t0 = c * 16;
        __syncthreads();
#pragma unroll
        for (int s = 0; s < 4; s++) {
            int idx = tid + s * 256;
            int r  = idx >> 6;
            int c4 = (idx & 63) << 2;
            *(float4*)&stage[r][c4] = *(const float4*)&kb[(size_t)(t0 + r) * DIN + c4];
        }
        __syncthreads();
#pragma unroll
        for (int tg = 0; tg < 4; tg++) {
            float kv0 = stage[tg * 4 + 0][ilane];
            float kv1 = stage[tg * 4 + 1][ilane];
            float kv2 = stage[tg * 4 + 2][ilane];
            float kv3 = stage[tg * 4 + 3][ilane];
#pragma unroll
            for (int q = 0; q < 8; q++) {
                float4 a = *(const float4*)&sc[q][t0 + tg * 4];  // broadcast
                ctx[q] = fmaf(a.x, kv0,
                         fmaf(a.y, kv1,
                         fmaf(a.z, kv2,
                         fmaf(a.w, kv3, ctx[q]))));
            }
        }
    }

#pragma unroll
    for (int q = 0; q < 8; q++)
        out[(size_t)(b * TQ + q0 + q) * DIN + ilane] = ctx[q];
}

// ---------------------------------------------------------------------------
// Launch. Inputs (metadata order): inputs, state, w1, w2, v, batch_size.
// Output: (B*TQ, DIN) float32.
// ---------------------------------------------------------------------------
extern "C" void kernel_launch(void* const* d_in, const int* in_sizes, int n_in,
                              void* d_out, int out_size)
{
    const float* inputs = (const float*)d_in[0];
    const float* state  = (const float*)d_in[1];
    const float* w1     = (const float*)d_in[2];
    const float* w2     = (const float*)d_in[3];
    const float* v      = (const float*)d_in[4];
    float* out = (float*)d_out;
    (void)in_sizes; (void)n_in; (void)out_size;

    dim3 g1(128 + 32, 4);      // 160 M-tiles x 4 N-tiles, 256 threads
    proj_gemm<<<g1, 256>>>(inputs, state, w1, w2);

    dim3 g2(TQ / 8, B_);       // (8, 32) blocks, 8 warps
    attn_kernel<<<g2, 256>>>(inputs, v, out);
}